// round 1
// baseline (speedup 1.0000x reference)
#include <cuda_runtime.h>
#include <cuda_bf16.h>
#include <cstdint>

// Problem constants (fixed by the reference)
#define BB 4
#define SS 2048
#define DD 1024
#define OO 1024
#define EE 16
#define KK 512

// ---------------- device scratch (no allocations allowed) ----------------
__device__ float g_logits[BB * EE * SS];   // logits transposed: [b][e][s]
__device__ int   g_idx  [BB * EE * KK];    // top-K token indices per (b,e)
__device__ float g_inv  [BB * EE * KK];    // 1 / softmax_prob for each selected token

// ============================================================================
// Kernel 1: gate logits, stored transposed as [b*E+e][s]
//   logits[b,s,e] = dot(x[b,s,:], gate_w[:,e]) + gate_b[e]
// One block per (b,s); 256 threads = 8 warps; each warp handles 2 experts.
// ============================================================================
__global__ __launch_bounds__(256) void gate_kernel(
    const float* __restrict__ x,
    const float* __restrict__ gw,
    const float* __restrict__ gb)
{
    int bs = blockIdx.x;              // 0 .. B*S-1
    int b  = bs / SS;
    int s  = bs % SS;

    __shared__ float sx[DD];
    const float* xr = x + (size_t)bs * DD;
    for (int i = threadIdx.x; i < DD; i += blockDim.x) sx[i] = xr[i];
    __syncthreads();

    int warp = threadIdx.x >> 5;
    int lane = threadIdx.x & 31;

    #pragma unroll
    for (int q = 0; q < 2; q++) {
        int e = warp * 2 + q;         // 8 warps * 2 = 16 experts
        float acc = 0.0f;
        for (int d = lane; d < DD; d += 32)
            acc += sx[d] * gw[d * EE + e];
        #pragma unroll
        for (int o = 16; o > 0; o >>= 1)
            acc += __shfl_xor_sync(0xffffffffu, acc, o);
        if (lane == 0)
            g_logits[((size_t)(b * EE + e)) * SS + s] = acc + gb[e];
    }
}

// ============================================================================
// Kernel 2: fused softmax-stats + top-K selection per (b,e).
// One block of 1024 threads per (b,e). Bitonic sort of 2048 (logit, idx)
// pairs, descending by value, ties -> lower index first (matches jax top_k
// boundary behavior). Then vals[k] = exp(l-max)/sumexp; store 1/vals.
// ============================================================================
__global__ __launch_bounds__(1024) void topk_kernel()
{
    int be = blockIdx.x;              // 0 .. 63  (= b*E + e)
    int t  = threadIdx.x;

    __shared__ float sv[2 * SS / 2 * 2];  // 2048 floats
    __shared__ int   si[2048];
    __shared__ float red[1024];

    const float* lp = g_logits + (size_t)be * SS;
    sv[t]        = lp[t];
    sv[t + 1024] = lp[t + 1024];
    si[t]        = t;
    si[t + 1024] = t + 1024;
    __syncthreads();

    // --- block max ---
    float m = fmaxf(sv[t], sv[t + 1024]);
    red[t] = m; __syncthreads();
    for (int s2 = 512; s2 > 0; s2 >>= 1) {
        if (t < s2) red[t] = fmaxf(red[t], red[t + s2]);
        __syncthreads();
    }
    float gmax = red[0]; __syncthreads();

    // --- block sum of exp(l - max) ---
    float se = expf(sv[t] - gmax) + expf(sv[t + 1024] - gmax);
    red[t] = se; __syncthreads();
    for (int s2 = 512; s2 > 0; s2 >>= 1) {
        if (t < s2) red[t] += red[t + s2];
        __syncthreads();
    }
    float gsum = red[0]; __syncthreads();

    // --- bitonic sort, descending by value, tie -> smaller index first ---
    for (int k = 2; k <= 2048; k <<= 1) {
        for (int j = k >> 1; j > 0; j >>= 1) {
            #pragma unroll 1
            for (int base = 0; base < 2048; base += 1024) {
                int i   = base + t;
                int ixj = i ^ j;
                if (ixj > i) {
                    float vi = sv[i],  vj = sv[ixj];
                    int   ii = si[i],  ij = si[ixj];
                    // "good" == element i correctly precedes element ixj
                    bool good = (vi > vj) || (vi == vj && ii < ij);
                    bool dir  = ((i & k) == 0);
                    bool swap = dir ? (!good) : good;
                    if (swap) {
                        sv[i] = vj; sv[ixj] = vi;
                        si[i] = ij; si[ixj] = ii;
                    }
                }
            }
            __syncthreads();
        }
    }

    if (t < KK) {
        float l = sv[t];
        g_idx[(size_t)be * KK + t] = si[t];
        // 1 / prob = sumexp * exp(max - l)
        g_inv[(size_t)be * KK + t] = gsum * expf(gmax - l);
    }
}

// ============================================================================
// Kernel 3: zero the output (harness poisons d_out).
// ============================================================================
__global__ void zero_kernel(float* __restrict__ out, size_t n)
{
    size_t i = (size_t)blockIdx.x * blockDim.x + threadIdx.x;
    size_t stride = (size_t)gridDim.x * blockDim.x;
    for (; i < n; i += stride) out[i] = 0.0f;
}

// ============================================================================
// Kernel 4: gathered GEMM + epilogue scatter-add.
//   For each (b,e): C[512,1024] = X[gather rows][1024] @ W[e][1024,1024]
//   out[b, tok, :] += (C + b[e]) * (1/val)
// 128x128 tile, BK=16, 256 threads, 8x8 register blocking, fp32.
// ============================================================================
#define BM 128
#define BN 128
#define BK2 16

__global__ __launch_bounds__(256) void moe_gemm_kernel(
    const float* __restrict__ x,
    const float* __restrict__ w,
    const float* __restrict__ bias,   // [E,1]
    float* __restrict__ out)
{
    int be = blockIdx.z;              // b*E + e
    int b  = be >> 4;
    int e  = be & 15;
    int m0 = blockIdx.y * BM;
    int n0 = blockIdx.x * BN;

    __shared__ float As[BK2][BM];
    __shared__ float Bs[BK2][BN];
    __shared__ int   stok[BM];
    __shared__ float sinv[BM];

    int tid = threadIdx.x;
    if (tid < BM) {
        stok[tid] = g_idx[(size_t)be * KK + m0 + tid];
        sinv[tid] = g_inv[(size_t)be * KK + m0 + tid];
    }
    __syncthreads();

    const float* xb = x + (size_t)b * SS * DD;
    const float* wb = w + (size_t)e * DD * OO;

    float acc[8][8];
    #pragma unroll
    for (int i = 0; i < 8; i++)
        #pragma unroll
        for (int j = 0; j < 8; j++) acc[i][j] = 0.0f;

    int tm = tid >> 4;   // 0..15 -> 8 rows each
    int tn = tid & 15;   // 0..15 -> 8 cols each

    for (int k0 = 0; k0 < DD; k0 += BK2) {
        // --- load A tile (gathered rows), transpose into As[k][m] ---
        #pragma unroll
        for (int q = 0; q < 2; q++) {
            int fid = tid * 2 + q;        // 0..511 float4s
            int row = fid >> 2;           // 0..127
            int kv  = fid & 3;            // 0..3 -> k offsets kv*4..kv*4+3
            const float4 v = *(const float4*)(xb + (size_t)stok[row] * DD + k0 + kv * 4);
            As[kv * 4 + 0][row] = v.x;
            As[kv * 4 + 1][row] = v.y;
            As[kv * 4 + 2][row] = v.z;
            As[kv * 4 + 3][row] = v.w;
        }
        // --- load B tile (coalesced along O) ---
        #pragma unroll
        for (int q = 0; q < 2; q++) {
            int fid = tid * 2 + q;        // 0..511
            int kr  = fid >> 5;           // 0..15
            int cv  = fid & 31;           // 0..31 -> cols cv*4..cv*4+3
            const float4 v = *(const float4*)(wb + (size_t)(k0 + kr) * OO + n0 + cv * 4);
            *(float4*)&Bs[kr][cv * 4] = v;
        }
        __syncthreads();

        #pragma unroll
        for (int kk = 0; kk < BK2; kk++) {
            float a[8], bv[8];
            *(float4*)(a)      = *(const float4*)&As[kk][tm * 8];
            *(float4*)(a + 4)  = *(const float4*)&As[kk][tm * 8 + 4];
            *(float4*)(bv)     = *(const float4*)&Bs[kk][tn * 8];
            *(float4*)(bv + 4) = *(const float4*)&Bs[kk][tn * 8 + 4];
            #pragma unroll
            for (int i = 0; i < 8; i++)
                #pragma unroll
                for (int j = 0; j < 8; j++)
                    acc[i][j] += a[i] * bv[j];
        }
        __syncthreads();
    }

    // --- epilogue: (acc + bias_e) * inv_val, scatter-add by token ---
    float beb = bias[e];
    #pragma unroll
    for (int i = 0; i < 8; i++) {
        int   row = tm * 8 + i;
        int   tok = stok[row];
        float inv = sinv[row];
        float* orow = out + ((size_t)b * SS + tok) * OO + n0 + tn * 8;
        #pragma unroll
        for (int j = 0; j < 8; j++)
            atomicAdd(&orow[j], (acc[i][j] + beb) * inv);
    }
}

// ============================================================================
// Launch
// ============================================================================
extern "C" void kernel_launch(void* const* d_in, const int* in_sizes, int n_in,
                              void* d_out, int out_size)
{
    const float* x   = (const float*)d_in[0];   // [B,S,D]
    const float* gw  = (const float*)d_in[1];   // [D,E]
    const float* gb  = (const float*)d_in[2];   // [E]
    const float* w   = (const float*)d_in[3];   // [E,D,O]
    const float* bia = (const float*)d_in[4];   // [E,1]
    float* out = (float*)d_out;                 // [B,S,O] fp32

    (void)in_sizes; (void)n_in;

    gate_kernel<<<BB * SS, 256>>>(x, gw, gb);
    topk_kernel<<<BB * EE, 1024>>>();
    {
        size_t n = (size_t)out_size;
        int blocks = (int)((n + 255) / 256);
        if (blocks > 4096) blocks = 4096;
        zero_kernel<<<blocks, 256>>>(out, n);
    }
    {
        dim3 grid(OO / BN, KK / BM, BB * EE);   // (8, 4, 64)
        moe_gemm_kernel<<<grid, 256>>>(x, w, bia, out);
    }
}

// round 4
// speedup vs baseline: 3.3316x; 3.3316x over previous
#include <cuda_runtime.h>
#include <cuda_fp16.h>
#include <cstdint>

// Problem constants
#define BB 4
#define SS 2048
#define DD 1024
#define OO 1024
#define EE 16
#define KK 512

// GEMM tiling (HMMA mma.sync path, baseline sm_100 ISA)
#define BM 128
#define BN 128
#define BK 64
#define NCH 16                     // 1024 / 64 k-chunks
#define STG 4
#define A_TILE 16384               // 128 x 64 halves
#define B_TILE 16384               // 64 x 128 halves (two 64x64 SW128 blocks)
#define STAGE_BYTES (A_TILE + B_TILE)        // 32768
#define SMEM_DYN (STAGE_BYTES * STG)         // 131072

// ---------------- device scratch ----------------
__device__ float g_logits[BB * EE * SS];
__device__ int   g_idx  [BB * EE * KK];
__device__ float g_inv  [BB * EE * KK];
// A images: [be(64)][mt(4)][kc(16)] tiles of [m=128][k=64] halves, SW128   (64 MB)
__device__ __align__(1024) unsigned char g_Ag[64u * 4u * 16u * A_TILE];
// B images: [e(16)][nt(8)][kc(16)] tiles: [h=2][k=64][n=64] halves, SW128  (32 MB)
__device__ __align__(1024) unsigned char g_wt[16u * 8u * 16u * B_TILE];

// ---------------- PTX helpers (baseline ISA only) ----------------
__device__ __forceinline__ uint32_t smem_u32(const void* p) {
    uint32_t a;
    asm("{ .reg .u64 t; cvta.to.shared.u64 t, %1; cvt.u32.u64 %0, t; }" : "=r"(a) : "l"(p));
    return a;
}
__device__ __forceinline__ void cp16(uint32_t dst, const void* src) {
    asm volatile("cp.async.cg.shared.global [%0], [%1], 16;" :: "r"(dst), "l"(src) : "memory");
}
__device__ __forceinline__ void cp_commit() {
    asm volatile("cp.async.commit_group;" ::: "memory");
}
template <int N> __device__ __forceinline__ void cp_wait() {
    asm volatile("cp.async.wait_group %0;" :: "n"(N) : "memory");
}
__device__ __forceinline__ void ldsm_x4(uint32_t* r, uint32_t addr) {
    asm volatile("ldmatrix.sync.aligned.m8n8.x4.shared.b16 {%0,%1,%2,%3}, [%4];"
        : "=r"(r[0]), "=r"(r[1]), "=r"(r[2]), "=r"(r[3]) : "r"(addr));
}
__device__ __forceinline__ void ldsm_x4_t(uint32_t* r, uint32_t addr) {
    asm volatile("ldmatrix.sync.aligned.m8n8.x4.trans.shared.b16 {%0,%1,%2,%3}, [%4];"
        : "=r"(r[0]), "=r"(r[1]), "=r"(r[2]), "=r"(r[3]) : "r"(addr));
}
__device__ __forceinline__ void mma16816(float* c, const uint32_t* a, uint32_t b0, uint32_t b1) {
    asm volatile(
        "mma.sync.aligned.m16n8k16.row.col.f32.f16.f16.f32 "
        "{%0,%1,%2,%3}, {%4,%5,%6,%7}, {%8,%9}, {%0,%1,%2,%3};"
        : "+f"(c[0]), "+f"(c[1]), "+f"(c[2]), "+f"(c[3])
        : "r"(a[0]), "r"(a[1]), "r"(a[2]), "r"(a[3]), "r"(b0), "r"(b1));
}
__device__ __forceinline__ int swz(int off) { return off ^ ((off >> 3) & 0x70); }

// ============================================================================
// Kernel 1: gate logits, stored transposed [b*E+e][s]
// ============================================================================
__global__ __launch_bounds__(256) void gate_kernel(
    const float* __restrict__ x, const float* __restrict__ gw, const float* __restrict__ gb)
{
    int bs = blockIdx.x;
    int b  = bs / SS;
    int s  = bs % SS;
    __shared__ float sx[DD];
    const float* xr = x + (size_t)bs * DD;
    for (int i = threadIdx.x; i < DD; i += blockDim.x) sx[i] = xr[i];
    __syncthreads();
    int warp = threadIdx.x >> 5, lane = threadIdx.x & 31;
    #pragma unroll
    for (int q = 0; q < 2; q++) {
        int e = warp * 2 + q;
        float acc = 0.0f;
        for (int d = lane; d < DD; d += 32) acc += sx[d] * gw[d * EE + e];
        #pragma unroll
        for (int o = 16; o > 0; o >>= 1) acc += __shfl_xor_sync(0xffffffffu, acc, o);
        if (lane == 0) g_logits[((size_t)(b * EE + e)) * SS + s] = acc + gb[e];
    }
}

// ============================================================================
// Kernel 2: softmax stats + exact top-K via bitonic sort per (b,e)
// ============================================================================
__global__ __launch_bounds__(1024) void topk_kernel()
{
    int be = blockIdx.x;
    int t  = threadIdx.x;
    __shared__ float sv[2048];
    __shared__ int   si[2048];
    __shared__ float red[1024];

    const float* lp = g_logits + (size_t)be * SS;
    sv[t] = lp[t]; sv[t + 1024] = lp[t + 1024];
    si[t] = t;     si[t + 1024] = t + 1024;
    __syncthreads();

    float m = fmaxf(sv[t], sv[t + 1024]);
    red[t] = m; __syncthreads();
    for (int s2 = 512; s2 > 0; s2 >>= 1) { if (t < s2) red[t] = fmaxf(red[t], red[t + s2]); __syncthreads(); }
    float gmax = red[0]; __syncthreads();

    float se = expf(sv[t] - gmax) + expf(sv[t + 1024] - gmax);
    red[t] = se; __syncthreads();
    for (int s2 = 512; s2 > 0; s2 >>= 1) { if (t < s2) red[t] += red[t + s2]; __syncthreads(); }
    float gsum = red[0]; __syncthreads();

    for (int k = 2; k <= 2048; k <<= 1) {
        for (int j = k >> 1; j > 0; j >>= 1) {
            #pragma unroll 1
            for (int base = 0; base < 2048; base += 1024) {
                int i = base + t, ixj = i ^ j;
                if (ixj > i) {
                    float vi = sv[i], vj = sv[ixj];
                    int   ii = si[i], ij = si[ixj];
                    bool good = (vi > vj) || (vi == vj && ii < ij);
                    bool dir  = ((i & k) == 0);
                    if (dir ? (!good) : good) {
                        sv[i] = vj; sv[ixj] = vi;
                        si[i] = ij; si[ixj] = ii;
                    }
                }
            }
            __syncthreads();
        }
    }
    if (t < KK) {
        g_idx[(size_t)be * KK + t] = si[t];
        g_inv[(size_t)be * KK + t] = gsum * expf(gmax - sv[t]);
    }
}

// ============================================================================
// Kernel 3: gather + convert x rows -> pre-swizzled fp16 A-tile images
// block = (be, mt); 256 threads
// ============================================================================
__global__ __launch_bounds__(256) void gather_kernel(const float* __restrict__ x)
{
    int be = blockIdx.x >> 2, mt = blockIdx.x & 3;
    int b  = be >> 4;
    const int* idx = g_idx + (size_t)be * KK + mt * 128;

    for (int kc = 0; kc < NCH; kc++) {
        unsigned char* tile = g_Ag + (((size_t)(be * 4 + mt) * NCH + kc) * A_TILE);
        for (int u = threadIdx.x; u < 1024; u += 256) {   // 128 rows x 8 16B-chunks
            int row = u >> 3, c16 = u & 7;
            int tok = idx[row];
            const float4* src = (const float4*)(x + ((size_t)b * SS + tok) * DD + kc * 64 + c16 * 8);
            float4 a = src[0], c = src[1];
            __half2 h0 = __floats2half2_rn(a.x, a.y);
            __half2 h1 = __floats2half2_rn(a.z, a.w);
            __half2 h2 = __floats2half2_rn(c.x, c.y);
            __half2 h3 = __floats2half2_rn(c.z, c.w);
            uint4 v;
            v.x = *(uint32_t*)&h0; v.y = *(uint32_t*)&h1;
            v.z = *(uint32_t*)&h2; v.w = *(uint32_t*)&h3;
            *(uint4*)(tile + swz(row * 128 + c16 * 16)) = v;
        }
    }
}

// ============================================================================
// Kernel 4: convert W -> pre-swizzled fp16 B-tile images (K-major, no transpose)
// B tile for (e, nt, kc): logical [k=64][n=128], stored as 2 blocks of
// [k=64][n=64] halves (128B rows), SW128-swizzled. block id = e*128 + nt*16 + kc.
// ============================================================================
__global__ __launch_bounds__(256) void convertw_kernel(const float* __restrict__ w)
{
    int blk = blockIdx.x;
    int kc = blk & 15, nt = (blk >> 4) & 7, e = blk >> 7;
    const float* src = w + ((size_t)e * DD + kc * 64) * OO + (size_t)nt * 128;
    unsigned char* tile = g_wt + (size_t)blk * B_TILE;

    #pragma unroll
    for (int it = 0; it < 4; it++) {
        int u = it * 256 + threadIdx.x;      // 0..1023 : k(64) x c16(16)
        int k = u >> 4, c16 = u & 15;
        const float4* s = (const float4*)(src + (size_t)k * OO + c16 * 8);
        float4 a = s[0], c = s[1];
        __half2 h0 = __floats2half2_rn(a.x, a.y);
        __half2 h1 = __floats2half2_rn(a.z, a.w);
        __half2 h2 = __floats2half2_rn(c.x, c.y);
        __half2 h3 = __floats2half2_rn(c.z, c.w);
        uint4 v;
        v.x = *(uint32_t*)&h0; v.y = *(uint32_t*)&h1;
        v.z = *(uint32_t*)&h2; v.w = *(uint32_t*)&h3;
        int h = c16 >> 3;
        *(uint4*)(tile + h * 8192 + swz(k * 128 + (c16 & 7) * 16)) = v;
    }
}

// ============================================================================
// Kernel 5: zero output (vectorized; out_size is a multiple of 4)
// ============================================================================
__global__ void zero_kernel(float4* __restrict__ out, size_t n4)
{
    size_t i = (size_t)blockIdx.x * blockDim.x + threadIdx.x;
    size_t stride = (size_t)gridDim.x * blockDim.x;
    float4 z = make_float4(0.f, 0.f, 0.f, 0.f);
    for (; i < n4; i += stride) out[i] = z;
}

// ============================================================================
// Kernel 6: HMMA GEMM (mma.sync m16n8k16) + scatter-add epilogue
// grid = (nt=8, mt=4, be=64); 256 threads = 8 warps in 4(m) x 2(n)
// ============================================================================
__global__ __launch_bounds__(256, 1) void gemm_kernel(
    const float* __restrict__ bias, float* __restrict__ out)
{
    extern __shared__ unsigned char smem[];
    uint32_t sbase = smem_u32(smem);

    int tid = threadIdx.x, wid = tid >> 5, lane = tid & 31;
    int nt = blockIdx.x, mt = blockIdx.y, be = blockIdx.z;
    int b = be >> 4, e = be & 15;

    const unsigned char* Abase = g_Ag + ((size_t)(be * 4 + mt) * NCH) * A_TILE;
    const unsigned char* Bbase = g_wt + ((size_t)(e * 8 + nt) * NCH) * B_TILE;

    int warp_m = wid >> 1, warp_n = wid & 1;
    int m_w = warp_m * 32, n_w = warp_n * 64;

    // Per-thread ldmatrix offsets within one stage buffer
    uint32_t offA[2][4], offB[4][4];
    #pragma unroll
    for (int mi = 0; mi < 2; mi++)
        #pragma unroll
        for (int ks = 0; ks < 4; ks++)
            offA[mi][ks] = swz((m_w + mi * 16 + (lane & 15)) * 128 + ks * 32 + (lane >> 4) * 16);
    #pragma unroll
    for (int p = 0; p < 4; p++)
        #pragma unroll
        for (int ks = 0; ks < 4; ks++)
            offB[p][ks] = (uint32_t)(A_TILE + warp_n * 8192 +
                          swz((ks * 16 + (lane & 15)) * 128 + p * 32 + (lane >> 4) * 16));

    float c[2][8][4];
    #pragma unroll
    for (int mi = 0; mi < 2; mi++)
        #pragma unroll
        for (int nj = 0; nj < 8; nj++)
            #pragma unroll
            for (int q = 0; q < 4; q++) c[mi][nj][q] = 0.0f;

    // stage loader: 2048 x 16B chunks, linear (images are pre-swizzled)
    auto load_stage = [&](int ch, int st) {
        const unsigned char* As = Abase + (size_t)ch * A_TILE;
        const unsigned char* Bs = Bbase + (size_t)ch * B_TILE;
        uint32_t dst = sbase + st * STAGE_BYTES;
        #pragma unroll
        for (int q = 0; q < 4; q++) {
            int cix = tid + q * 256;
            cp16(dst + cix * 16, As + (size_t)cix * 16);
        }
        #pragma unroll
        for (int q = 0; q < 4; q++) {
            int cix = tid + q * 256;
            cp16(dst + A_TILE + cix * 16, Bs + (size_t)cix * 16);
        }
    };

    // prologue: stages 0..2
    #pragma unroll
    for (int s = 0; s < STG - 1; s++) { load_stage(s, s); cp_commit(); }

    for (int i = 0; i < NCH; i++) {
        cp_wait<STG - 2>();
        __syncthreads();

        uint32_t sb = sbase + (i & (STG - 1)) * STAGE_BYTES;
        #pragma unroll
        for (int ks = 0; ks < 4; ks++) {
            uint32_t a[2][4], bf[4][4];
            ldsm_x4(a[0], sb + offA[0][ks]);
            ldsm_x4(a[1], sb + offA[1][ks]);
            #pragma unroll
            for (int p = 0; p < 4; p++) ldsm_x4_t(bf[p], sb + offB[p][ks]);
            #pragma unroll
            for (int mi = 0; mi < 2; mi++)
                #pragma unroll
                for (int p = 0; p < 4; p++) {
                    mma16816(c[mi][2 * p],     a[mi], bf[p][0], bf[p][1]);
                    mma16816(c[mi][2 * p + 1], a[mi], bf[p][2], bf[p][3]);
                }
        }
        __syncthreads();

        if (i + STG - 1 < NCH) load_stage(i + STG - 1, (i + STG - 1) & (STG - 1));
        cp_commit();
    }

    // -------- epilogue: (c + bias) * inv, scatter-add by token --------
    float bi = bias[e];
    #pragma unroll
    for (int mi = 0; mi < 2; mi++) {
        #pragma unroll
        for (int r = 0; r < 2; r++) {
            int mrow = m_w + mi * 16 + r * 8 + (lane >> 2);
            int gm   = mt * 128 + mrow;
            int tok  = g_idx[(size_t)be * KK + gm];
            float inv = g_inv[(size_t)be * KK + gm];
            float* orow = out + ((size_t)b * SS + tok) * OO + nt * 128 + n_w + (lane & 3) * 2;
            #pragma unroll
            for (int nj = 0; nj < 8; nj++) {
                atomicAdd(&orow[nj * 8],     (c[mi][nj][r * 2]     + bi) * inv);
                atomicAdd(&orow[nj * 8 + 1], (c[mi][nj][r * 2 + 1] + bi) * inv);
            }
        }
    }
}

// ============================================================================
// Launch
// ============================================================================
extern "C" void kernel_launch(void* const* d_in, const int* in_sizes, int n_in,
                              void* d_out, int out_size)
{
    const float* x   = (const float*)d_in[0];   // [B,S,D]
    const float* gw  = (const float*)d_in[1];   // [D,E]
    const float* gb  = (const float*)d_in[2];   // [E]
    const float* w   = (const float*)d_in[3];   // [E,D,O]
    const float* bia = (const float*)d_in[4];   // [E,1]
    float* out = (float*)d_out;
    (void)in_sizes; (void)n_in;

    cudaFuncSetAttribute(gemm_kernel, cudaFuncAttributeMaxDynamicSharedMemorySize, SMEM_DYN);

    gate_kernel<<<BB * SS, 256>>>(x, gw, gb);
    convertw_kernel<<<EE * 8 * NCH, 256>>>(w);
    topk_kernel<<<BB * EE, 1024>>>();
    gather_kernel<<<BB * EE * 4, 256>>>(x);
    {
        size_t n4 = (size_t)out_size / 4;
        int blocks = (int)((n4 + 255) / 256);
        if (blocks > 2048) blocks = 2048;
        zero_kernel<<<blocks, 256>>>((float4*)out, n4);
    }
    {
        dim3 grid(OO / BN, KK / BM, BB * EE);   // (8, 4, 64)
        gemm_kernel<<<grid, 256, SMEM_DYN>>>(bia, out);
    }
}

// round 6
// speedup vs baseline: 3.9459x; 1.1844x over previous
#include <cuda_runtime.h>
#include <cuda_fp16.h>
#include <cstdint>

// Problem constants
#define BB 4
#define SS 2048
#define DD 1024
#define OO 1024
#define EE 16
#define KK 512

// GEMM tiling (HMMA mma.sync path, baseline sm_100 ISA)
#define BM 128
#define BN 128
#define BK 64
#define NCH 16                     // 1024 / 64 k-chunks
#define STG 3
#define A_TILE 16384               // 128 x 64 halves
#define B_TILE 16384               // 64 x 128 halves (two 64x64 SW128 blocks)
#define STAGE_BYTES (A_TILE + B_TILE)        // 32768
#define SMEM_DYN (STAGE_BYTES * STG)         // 98304

// ---------------- device scratch ----------------
__device__ float g_logits[BB * EE * SS];
__device__ int   g_idx  [BB * EE * KK];
__device__ float g_inv  [BB * EE * KK];
// A images: [be(64)][mt(4)][kc(16)] tiles of [m=128][k=64] halves, SW128   (64 MB)
__device__ __align__(1024) unsigned char g_Ag[64u * 4u * 16u * A_TILE];
// B images: [e(16)][nt(8)][kc(16)] tiles: [h=2][k=64][n=64] halves, SW128  (32 MB)
__device__ __align__(1024) unsigned char g_wt[16u * 8u * 16u * B_TILE];

// ---------------- PTX helpers (baseline ISA only) ----------------
__device__ __forceinline__ uint32_t smem_u32(const void* p) {
    uint32_t a;
    asm("{ .reg .u64 t; cvta.to.shared.u64 t, %1; cvt.u32.u64 %0, t; }" : "=r"(a) : "l"(p));
    return a;
}
__device__ __forceinline__ void cp16(uint32_t dst, const void* src) {
    asm volatile("cp.async.cg.shared.global [%0], [%1], 16;" :: "r"(dst), "l"(src) : "memory");
}
__device__ __forceinline__ void cp_commit() {
    asm volatile("cp.async.commit_group;" ::: "memory");
}
template <int N> __device__ __forceinline__ void cp_wait() {
    asm volatile("cp.async.wait_group %0;" :: "n"(N) : "memory");
}
__device__ __forceinline__ void ldsm_x4(uint32_t* r, uint32_t addr) {
    asm volatile("ldmatrix.sync.aligned.m8n8.x4.shared.b16 {%0,%1,%2,%3}, [%4];"
        : "=r"(r[0]), "=r"(r[1]), "=r"(r[2]), "=r"(r[3]) : "r"(addr));
}
__device__ __forceinline__ void ldsm_x4_t(uint32_t* r, uint32_t addr) {
    asm volatile("ldmatrix.sync.aligned.m8n8.x4.trans.shared.b16 {%0,%1,%2,%3}, [%4];"
        : "=r"(r[0]), "=r"(r[1]), "=r"(r[2]), "=r"(r[3]) : "r"(addr));
}
__device__ __forceinline__ void mma16816(float* c, const uint32_t* a, uint32_t b0, uint32_t b1) {
    asm volatile(
        "mma.sync.aligned.m16n8k16.row.col.f32.f16.f16.f32 "
        "{%0,%1,%2,%3}, {%4,%5,%6,%7}, {%8,%9}, {%0,%1,%2,%3};"
        : "+f"(c[0]), "+f"(c[1]), "+f"(c[2]), "+f"(c[3])
        : "r"(a[0]), "r"(a[1]), "r"(a[2]), "r"(a[3]), "r"(b0), "r"(b1));
}
__device__ __forceinline__ void red2(float* ptr, float a, float b) {
    asm volatile("red.global.add.v2.f32 [%0], {%1, %2};"
        :: "l"(ptr), "f"(a), "f"(b) : "memory");
}
__device__ __forceinline__ int swz(int off) { return off ^ ((off >> 3) & 0x70); }

// ============================================================================
// Kernel 1: gate logits, stored transposed [b*E+e][s]
// ============================================================================
__global__ __launch_bounds__(256) void gate_kernel(
    const float* __restrict__ x, const float* __restrict__ gw, const float* __restrict__ gb)
{
    int bs = blockIdx.x;
    int b  = bs / SS;
    int s  = bs % SS;
    __shared__ float sx[DD];
    const float* xr = x + (size_t)bs * DD;
    for (int i = threadIdx.x; i < DD; i += blockDim.x) sx[i] = xr[i];
    __syncthreads();
    int warp = threadIdx.x >> 5, lane = threadIdx.x & 31;
    #pragma unroll
    for (int q = 0; q < 2; q++) {
        int e = warp * 2 + q;
        float acc = 0.0f;
        for (int d = lane; d < DD; d += 32) acc += sx[d] * gw[d * EE + e];
        #pragma unroll
        for (int o = 16; o > 0; o >>= 1) acc += __shfl_xor_sync(0xffffffffu, acc, o);
        if (lane == 0) g_logits[((size_t)(b * EE + e)) * SS + s] = acc + gb[e];
    }
}

// ============================================================================
// Kernel 2: softmax stats + exact top-K via bitonic sort per (b,e)
// ============================================================================
__global__ __launch_bounds__(1024) void topk_kernel()
{
    int be = blockIdx.x;
    int t  = threadIdx.x;
    __shared__ float sv[2048];
    __shared__ int   si[2048];
    __shared__ float red[1024];

    const float* lp = g_logits + (size_t)be * SS;
    sv[t] = lp[t]; sv[t + 1024] = lp[t + 1024];
    si[t] = t;     si[t + 1024] = t + 1024;
    __syncthreads();

    float m = fmaxf(sv[t], sv[t + 1024]);
    red[t] = m; __syncthreads();
    for (int s2 = 512; s2 > 0; s2 >>= 1) { if (t < s2) red[t] = fmaxf(red[t], red[t + s2]); __syncthreads(); }
    float gmax = red[0]; __syncthreads();

    float se = expf(sv[t] - gmax) + expf(sv[t + 1024] - gmax);
    red[t] = se; __syncthreads();
    for (int s2 = 512; s2 > 0; s2 >>= 1) { if (t < s2) red[t] += red[t + s2]; __syncthreads(); }
    float gsum = red[0]; __syncthreads();

    for (int k = 2; k <= 2048; k <<= 1) {
        for (int j = k >> 1; j > 0; j >>= 1) {
            #pragma unroll 1
            for (int base = 0; base < 2048; base += 1024) {
                int i = base + t, ixj = i ^ j;
                if (ixj > i) {
                    float vi = sv[i], vj = sv[ixj];
                    int   ii = si[i], ij = si[ixj];
                    bool good = (vi > vj) || (vi == vj && ii < ij);
                    bool dir  = ((i & k) == 0);
                    if (dir ? (!good) : good) {
                        sv[i] = vj; sv[ixj] = vi;
                        si[i] = ij; si[ixj] = ii;
                    }
                }
            }
            __syncthreads();
        }
    }
    if (t < KK) {
        g_idx[(size_t)be * KK + t] = si[t];
        g_inv[(size_t)be * KK + t] = gsum * expf(gmax - sv[t]);
    }
}

// ============================================================================
// Kernel 3: gather + convert x rows -> pre-swizzled fp16 A-tile images
// block = (be, mt, kc); 256 threads, 4 chunks each
// ============================================================================
__global__ __launch_bounds__(256) void gather_kernel(const float* __restrict__ x)
{
    int blk = blockIdx.x;                 // be*64 + mt*16 + kc
    int kc = blk & 15, mt = (blk >> 4) & 3, be = blk >> 6;
    int b  = be >> 4;
    const int* idx = g_idx + (size_t)be * KK + mt * 128;

    unsigned char* tile = g_Ag + (((size_t)(be * 4 + mt) * NCH + kc) * A_TILE);
    #pragma unroll
    for (int it = 0; it < 4; it++) {
        int u = it * 256 + threadIdx.x;   // 0..1023: 128 rows x 8 16B-chunks
        int row = u >> 3, c16 = u & 7;
        int tok = idx[row];
        const float4* src = (const float4*)(x + ((size_t)b * SS + tok) * DD + kc * 64 + c16 * 8);
        float4 a = src[0], c = src[1];
        __half2 h0 = __floats2half2_rn(a.x, a.y);
        __half2 h1 = __floats2half2_rn(a.z, a.w);
        __half2 h2 = __floats2half2_rn(c.x, c.y);
        __half2 h3 = __floats2half2_rn(c.z, c.w);
        uint4 v;
        v.x = *(uint32_t*)&h0; v.y = *(uint32_t*)&h1;
        v.z = *(uint32_t*)&h2; v.w = *(uint32_t*)&h3;
        *(uint4*)(tile + swz(row * 128 + c16 * 16)) = v;
    }
}

// ============================================================================
// Kernel 4: convert W -> pre-swizzled fp16 B-tile images (K-major)
// ============================================================================
__global__ __launch_bounds__(256) void convertw_kernel(const float* __restrict__ w)
{
    int blk = blockIdx.x;
    int kc = blk & 15, nt = (blk >> 4) & 7, e = blk >> 7;
    const float* src = w + ((size_t)e * DD + kc * 64) * OO + (size_t)nt * 128;
    unsigned char* tile = g_wt + (size_t)blk * B_TILE;

    #pragma unroll
    for (int it = 0; it < 4; it++) {
        int u = it * 256 + threadIdx.x;      // 0..1023 : k(64) x c16(16)
        int k = u >> 4, c16 = u & 15;
        const float4* s = (const float4*)(src + (size_t)k * OO + c16 * 8);
        float4 a = s[0], c = s[1];
        __half2 h0 = __floats2half2_rn(a.x, a.y);
        __half2 h1 = __floats2half2_rn(a.z, a.w);
        __half2 h2 = __floats2half2_rn(c.x, c.y);
        __half2 h3 = __floats2half2_rn(c.z, c.w);
        uint4 v;
        v.x = *(uint32_t*)&h0; v.y = *(uint32_t*)&h1;
        v.z = *(uint32_t*)&h2; v.w = *(uint32_t*)&h3;
        int h = c16 >> 3;
        *(uint4*)(tile + h * 8192 + swz(k * 128 + (c16 & 7) * 16)) = v;
    }
}

// ============================================================================
// Kernel 5: zero output (vectorized)
// ============================================================================
__global__ void zero_kernel(float4* __restrict__ out, size_t n4)
{
    size_t i = (size_t)blockIdx.x * blockDim.x + threadIdx.x;
    size_t stride = (size_t)gridDim.x * blockDim.x;
    float4 z = make_float4(0.f, 0.f, 0.f, 0.f);
    for (; i < n4; i += stride) out[i] = z;
}

// ============================================================================
// Kernel 6: HMMA GEMM (mma.sync m16n8k16) + red.v2 scatter-add epilogue
// grid = (nt=8, mt=4, be=64); 256 threads = 8 warps in 4(m) x 2(n); 2 CTAs/SM
// ============================================================================
__global__ __launch_bounds__(256, 2) void gemm_kernel(
    const float* __restrict__ bias, float* __restrict__ out)
{
    extern __shared__ unsigned char smem[];
    uint32_t sbase = smem_u32(smem);

    int tid = threadIdx.x, wid = tid >> 5, lane = tid & 31;
    int nt = blockIdx.x, mt = blockIdx.y, be = blockIdx.z;
    int b = be >> 4, e = be & 15;

    const unsigned char* Abase = g_Ag + ((size_t)(be * 4 + mt) * NCH) * A_TILE;
    const unsigned char* Bbase = g_wt + ((size_t)(e * 8 + nt) * NCH) * B_TILE;

    int warp_m = wid >> 1, warp_n = wid & 1;
    int m_w = warp_m * 32, n_w = warp_n * 64;

    // Compact ldmatrix offsets: swz(off + v*32) == swz(off) ^ (v<<5)
    // (v*32 only touches bits 5-6; SW128 mask depends only on the row)
    uint32_t offA[2];   // per mi, ks=0; vary ks via ^(ks<<5)
    #pragma unroll
    for (int mi = 0; mi < 2; mi++)
        offA[mi] = swz((m_w + mi * 16 + (lane & 15)) * 128 + (lane >> 4) * 16);
    uint32_t offB[4];   // per ks, p=0; vary p via ^(p<<5)
    #pragma unroll
    for (int ks = 0; ks < 4; ks++)
        offB[ks] = (uint32_t)(A_TILE + warp_n * 8192 +
                   swz((ks * 16 + (lane & 15)) * 128 + (lane >> 4) * 16));

    float c[2][8][4];
    #pragma unroll
    for (int mi = 0; mi < 2; mi++)
        #pragma unroll
        for (int nj = 0; nj < 8; nj++)
            #pragma unroll
            for (int q = 0; q < 4; q++) c[mi][nj][q] = 0.0f;

    // stage loader: 2048 x 16B chunks, linear (images are pre-swizzled)
    auto load_stage = [&](int ch, int st) {
        const unsigned char* As = Abase + (size_t)ch * A_TILE;
        const unsigned char* Bs = Bbase + (size_t)ch * B_TILE;
        uint32_t dst = sbase + st * STAGE_BYTES;
        #pragma unroll
        for (int q = 0; q < 4; q++) {
            int cix = tid + q * 256;
            cp16(dst + cix * 16, As + (size_t)cix * 16);
        }
        #pragma unroll
        for (int q = 0; q < 4; q++) {
            int cix = tid + q * 256;
            cp16(dst + A_TILE + cix * 16, Bs + (size_t)cix * 16);
        }
    };

    // prologue: stages 0..STG-2
    #pragma unroll
    for (int s = 0; s < STG - 1; s++) { load_stage(s, s); cp_commit(); }

    int st = 0;
    for (int i = 0; i < NCH; i++) {
        cp_wait<STG - 2>();
        __syncthreads();

        uint32_t sb = sbase + st * STAGE_BYTES;
        #pragma unroll
        for (int ks = 0; ks < 4; ks++) {
            uint32_t a[2][4], bf[4][4];
            ldsm_x4(a[0], sb + (offA[0] ^ (ks << 5)));
            ldsm_x4(a[1], sb + (offA[1] ^ (ks << 5)));
            #pragma unroll
            for (int p = 0; p < 4; p++) ldsm_x4_t(bf[p], sb + (offB[ks] ^ (p << 5)));
            #pragma unroll
            for (int mi = 0; mi < 2; mi++)
                #pragma unroll
                for (int p = 0; p < 4; p++) {
                    mma16816(c[mi][2 * p],     a[mi], bf[p][0], bf[p][1]);
                    mma16816(c[mi][2 * p + 1], a[mi], bf[p][2], bf[p][3]);
                }
        }
        // Refill target is the stage consumed in iteration i-1; every thread
        // passed the barrier above after finishing it, so no second sync.
        if (i + STG - 1 < NCH) {
            int nst = st + STG - 1; if (nst >= STG) nst -= STG;
            load_stage(i + STG - 1, nst);
        }
        cp_commit();
        if (++st == STG) st = 0;
    }

    // -------- epilogue: (c + bias) * inv, red.v2 scatter-add by token --------
    float bi = bias[e];
    #pragma unroll
    for (int mi = 0; mi < 2; mi++) {
        #pragma unroll
        for (int r = 0; r < 2; r++) {
            int mrow = m_w + mi * 16 + r * 8 + (lane >> 2);
            int gm   = mt * 128 + mrow;
            int tok  = g_idx[(size_t)be * KK + gm];
            float inv = g_inv[(size_t)be * KK + gm];
            float* orow = out + ((size_t)b * SS + tok) * OO + nt * 128 + n_w + (lane & 3) * 2;
            #pragma unroll
            for (int nj = 0; nj < 8; nj++)
                red2(&orow[nj * 8],
                     (c[mi][nj][r * 2]     + bi) * inv,
                     (c[mi][nj][r * 2 + 1] + bi) * inv);
        }
    }
}

// ============================================================================
// Launch
// ============================================================================
extern "C" void kernel_launch(void* const* d_in, const int* in_sizes, int n_in,
                              void* d_out, int out_size)
{
    const float* x   = (const float*)d_in[0];   // [B,S,D]
    const float* gw  = (const float*)d_in[1];   // [D,E]
    const float* gb  = (const float*)d_in[2];   // [E]
    const float* w   = (const float*)d_in[3];   // [E,D,O]
    const float* bia = (const float*)d_in[4];   // [E,1]
    float* out = (float*)d_out;
    (void)in_sizes; (void)n_in;

    cudaFuncSetAttribute(gemm_kernel, cudaFuncAttributeMaxDynamicSharedMemorySize, SMEM_DYN);

    gate_kernel<<<BB * SS, 256>>>(x, gw, gb);
    convertw_kernel<<<EE * 8 * NCH, 256>>>(w);
    topk_kernel<<<BB * EE, 1024>>>();
    gather_kernel<<<BB * EE * 4 * NCH, 256>>>(x);
    {
        size_t n4 = (size_t)out_size / 4;
        int blocks = (int)((n4 + 255) / 256);
        if (blocks > 2048) blocks = 2048;
        zero_kernel<<<blocks, 256>>>((float4*)out, n4);
    }
    {
        dim3 grid(OO / BN, KK / BM, BB * EE);   // (8, 4, 64)
        gemm_kernel<<<grid, 256, SMEM_DYN>>>(bia, out);
    }
}

// round 8
// speedup vs baseline: 4.0352x; 1.0226x over previous
#include <cuda_runtime.h>
#include <cuda_fp16.h>
#include <cstdint>

// Problem constants
#define BB 4
#define SS 2048
#define DD 1024
#define OO 1024
#define EE 16
#define KK 512

// GEMM tiling (HMMA mma.sync path, baseline sm_100 ISA)
#define BM 128
#define BN 128
#define BK 64
#define NCH 16                     // 1024 / 64 k-chunks
#define STG 3
#define A_TILE 16384               // 128 x 64 halves
#define B_TILE 16384               // 64 x 128 halves (two 64x64 SW128 blocks)
#define STAGE_BYTES (A_TILE + B_TILE)        // 32768
#define SMEM_DYN (STAGE_BYTES * STG)         // 98304

// ---------------- device scratch ----------------
__device__ float g_logits[BB * EE * SS];
__device__ int   g_idx  [BB * EE * KK];
__device__ float g_inv  [BB * EE * KK];
// A images: [be(64)][mt(4)][kc(16)] tiles of [m=128][k=64] halves, SW128   (64 MB)
__device__ __align__(1024) unsigned char g_Ag[64u * 4u * 16u * A_TILE];
// B images: [e(16)][nt(8)][kc(16)] tiles: [h=2][k=64][n=64] halves, SW128  (32 MB)
__device__ __align__(1024) unsigned char g_wt[16u * 8u * 16u * B_TILE];

// ---------------- PTX helpers (baseline ISA only) ----------------
__device__ __forceinline__ uint32_t smem_u32(const void* p) {
    uint32_t a;
    asm("{ .reg .u64 t; cvta.to.shared.u64 t, %1; cvt.u32.u64 %0, t; }" : "=r"(a) : "l"(p));
    return a;
}
__device__ __forceinline__ void cp16(uint32_t dst, const void* src) {
    asm volatile("cp.async.cg.shared.global [%0], [%1], 16;" :: "r"(dst), "l"(src) : "memory");
}
__device__ __forceinline__ void cp_commit() {
    asm volatile("cp.async.commit_group;" ::: "memory");
}
template <int N> __device__ __forceinline__ void cp_wait() {
    asm volatile("cp.async.wait_group %0;" :: "n"(N) : "memory");
}
__device__ __forceinline__ void ldsm_x4(uint32_t* r, uint32_t addr) {
    asm volatile("ldmatrix.sync.aligned.m8n8.x4.shared.b16 {%0,%1,%2,%3}, [%4];"
        : "=r"(r[0]), "=r"(r[1]), "=r"(r[2]), "=r"(r[3]) : "r"(addr));
}
__device__ __forceinline__ void ldsm_x4_t(uint32_t* r, uint32_t addr) {
    asm volatile("ldmatrix.sync.aligned.m8n8.x4.trans.shared.b16 {%0,%1,%2,%3}, [%4];"
        : "=r"(r[0]), "=r"(r[1]), "=r"(r[2]), "=r"(r[3]) : "r"(addr));
}
__device__ __forceinline__ void mma16816(float* c, const uint32_t* a, uint32_t b0, uint32_t b1) {
    asm volatile(
        "mma.sync.aligned.m16n8k16.row.col.f32.f16.f16.f32 "
        "{%0,%1,%2,%3}, {%4,%5,%6,%7}, {%8,%9}, {%0,%1,%2,%3};"
        : "+f"(c[0]), "+f"(c[1]), "+f"(c[2]), "+f"(c[3])
        : "r"(a[0]), "r"(a[1]), "r"(a[2]), "r"(a[3]), "r"(b0), "r"(b1));
}
__device__ __forceinline__ void red2(float* ptr, float a, float b) {
    asm volatile("red.global.add.v2.f32 [%0], {%1, %2};"
        :: "l"(ptr), "f"(a), "f"(b) : "memory");
}
__device__ __forceinline__ int swz(int off) { return off ^ ((off >> 3) & 0x70); }

// ============================================================================
// Kernel 1 (fused prep):
//   blocks [0, 8192): gate logits for bs=blockIdx (transposed store) + zero
//                     the matching out row (1024 floats = 256 float4).
//   blocks [8192, 10240): convert W -> pre-swizzled fp16 B-tile images.
// ============================================================================
__global__ __launch_bounds__(256) void prep_kernel(
    const float* __restrict__ x, const float* __restrict__ gw,
    const float* __restrict__ gb, const float* __restrict__ w,
    float* __restrict__ out)
{
    if (blockIdx.x < BB * SS) {
        // ---- gate + zero ----
        int bs = blockIdx.x;
        int b  = bs / SS;
        int s  = bs % SS;

        // zero this token's output row
        float4* orow = (float4*)(out + (size_t)bs * OO);
        orow[threadIdx.x] = make_float4(0.f, 0.f, 0.f, 0.f);

        __shared__ float sx[DD];
        const float* xr = x + (size_t)bs * DD;
        for (int i = threadIdx.x; i < DD; i += blockDim.x) sx[i] = xr[i];
        __syncthreads();
        int warp = threadIdx.x >> 5, lane = threadIdx.x & 31;
        #pragma unroll
        for (int q = 0; q < 2; q++) {
            int e = warp * 2 + q;
            float acc = 0.0f;
            for (int d = lane; d < DD; d += 32) acc += sx[d] * gw[d * EE + e];
            #pragma unroll
            for (int o = 16; o > 0; o >>= 1) acc += __shfl_xor_sync(0xffffffffu, acc, o);
            if (lane == 0) g_logits[((size_t)(b * EE + e)) * SS + s] = acc + gb[e];
        }
    } else {
        // ---- W conversion ----
        int blk = blockIdx.x - BB * SS;
        int kc = blk & 15, nt = (blk >> 4) & 7, e = blk >> 7;
        const float* src = w + ((size_t)e * DD + kc * 64) * OO + (size_t)nt * 128;
        unsigned char* tile = g_wt + (size_t)blk * B_TILE;

        #pragma unroll
        for (int it = 0; it < 4; it++) {
            int u = it * 256 + threadIdx.x;      // 0..1023 : k(64) x c16(16)
            int k = u >> 4, c16 = u & 15;
            const float4* sp = (const float4*)(src + (size_t)k * OO + c16 * 8);
            float4 a = sp[0], c = sp[1];
            __half2 h0 = __floats2half2_rn(a.x, a.y);
            __half2 h1 = __floats2half2_rn(a.z, a.w);
            __half2 h2 = __floats2half2_rn(c.x, c.y);
            __half2 h3 = __floats2half2_rn(c.z, c.w);
            uint4 v;
            v.x = *(uint32_t*)&h0; v.y = *(uint32_t*)&h1;
            v.z = *(uint32_t*)&h2; v.w = *(uint32_t*)&h3;
            int h = c16 >> 3;
            *(uint4*)(tile + h * 8192 + swz(k * 128 + (c16 & 7) * 16)) = v;
        }
    }
}

// ============================================================================
// Kernel 2: softmax stats + exact top-K via bitonic sort per (b,e)
// ============================================================================
__global__ __launch_bounds__(1024) void topk_kernel()
{
    int be = blockIdx.x;
    int t  = threadIdx.x;
    __shared__ float sv[2048];
    __shared__ int   si[2048];
    __shared__ float red[1024];

    const float* lp = g_logits + (size_t)be * SS;
    sv[t] = lp[t]; sv[t + 1024] = lp[t + 1024];
    si[t] = t;     si[t + 1024] = t + 1024;
    __syncthreads();

    float m = fmaxf(sv[t], sv[t + 1024]);
    red[t] = m; __syncthreads();
    for (int s2 = 512; s2 > 0; s2 >>= 1) { if (t < s2) red[t] = fmaxf(red[t], red[t + s2]); __syncthreads(); }
    float gmax = red[0]; __syncthreads();

    float se = expf(sv[t] - gmax) + expf(sv[t + 1024] - gmax);
    red[t] = se; __syncthreads();
    for (int s2 = 512; s2 > 0; s2 >>= 1) { if (t < s2) red[t] += red[t + s2]; __syncthreads(); }
    float gsum = red[0]; __syncthreads();

    for (int k = 2; k <= 2048; k <<= 1) {
        for (int j = k >> 1; j > 0; j >>= 1) {
            #pragma unroll 1
            for (int base = 0; base < 2048; base += 1024) {
                int i = base + t, ixj = i ^ j;
                if (ixj > i) {
                    float vi = sv[i], vj = sv[ixj];
                    int   ii = si[i], ij = si[ixj];
                    bool good = (vi > vj) || (vi == vj && ii < ij);
                    bool dir  = ((i & k) == 0);
                    if (dir ? (!good) : good) {
                        sv[i] = vj; sv[ixj] = vi;
                        si[i] = ij; si[ixj] = ii;
                    }
                }
            }
            __syncthreads();
        }
    }
    if (t < KK) {
        g_idx[(size_t)be * KK + t] = si[t];
        g_inv[(size_t)be * KK + t] = gsum * expf(gmax - sv[t]);
    }
}

// ============================================================================
// Kernel 3: gather + convert x rows -> pre-swizzled fp16 A-tile images
// block = (be, mt, kc); 256 threads
// ============================================================================
__global__ __launch_bounds__(256) void gather_kernel(const float* __restrict__ x)
{
    int blk = blockIdx.x;                 // be*64 + mt*16 + kc
    int kc = blk & 15, mt = (blk >> 4) & 3, be = blk >> 6;
    int b  = be >> 4;
    const int* idx = g_idx + (size_t)be * KK + mt * 128;

    unsigned char* tile = g_Ag + (((size_t)(be * 4 + mt) * NCH + kc) * A_TILE);
    #pragma unroll
    for (int it = 0; it < 4; it++) {
        int u = it * 256 + threadIdx.x;   // 0..1023: 128 rows x 8 16B-chunks
        int row = u >> 3, c16 = u & 7;
        int tok = idx[row];
        const float4* src = (const float4*)(x + ((size_t)b * SS + tok) * DD + kc * 64 + c16 * 8);
        float4 a = src[0], c = src[1];
        __half2 h0 = __floats2half2_rn(a.x, a.y);
        __half2 h1 = __floats2half2_rn(a.z, a.w);
        __half2 h2 = __floats2half2_rn(c.x, c.y);
        __half2 h3 = __floats2half2_rn(c.z, c.w);
        uint4 v;
        v.x = *(uint32_t*)&h0; v.y = *(uint32_t*)&h1;
        v.z = *(uint32_t*)&h2; v.w = *(uint32_t*)&h3;
        *(uint4*)(tile + swz(row * 128 + c16 * 16)) = v;
    }
}

// ============================================================================
// Kernel 4: HMMA GEMM (mma.sync m16n8k16) + red.v2 scatter-add epilogue
// grid = (nt=8, mt=4, be=64); 256 threads = 8 warps in 4(m) x 2(n); 2 CTAs/SM
// ============================================================================
__global__ __launch_bounds__(256, 2) void gemm_kernel(
    const float* __restrict__ bias, float* __restrict__ out)
{
    extern __shared__ unsigned char smem[];
    uint32_t sbase = smem_u32(smem);

    int tid = threadIdx.x, wid = tid >> 5, lane = tid & 31;
    int nt = blockIdx.x, mt = blockIdx.y, be = blockIdx.z;
    int b = be >> 4, e = be & 15;

    const unsigned char* Abase = g_Ag + ((size_t)(be * 4 + mt) * NCH) * A_TILE;
    const unsigned char* Bbase = g_wt + ((size_t)(e * 8 + nt) * NCH) * B_TILE;

    int warp_m = wid >> 1, warp_n = wid & 1;
    int m_w = warp_m * 32, n_w = warp_n * 64;

    // Compact ldmatrix offsets: swz(off + v*32) == swz(off) ^ (v<<5)
    uint32_t offA[2];   // per mi, ks=0; vary ks via ^(ks<<5)
    #pragma unroll
    for (int mi = 0; mi < 2; mi++)
        offA[mi] = swz((m_w + mi * 16 + (lane & 15)) * 128 + (lane >> 4) * 16);
    uint32_t offB[4];   // per ks, p=0; vary p via ^(p<<5)
    #pragma unroll
    for (int ks = 0; ks < 4; ks++)
        offB[ks] = (uint32_t)(A_TILE + warp_n * 8192 +
                   swz((ks * 16 + (lane & 15)) * 128 + (lane >> 4) * 16));

    float c[2][8][4];
    #pragma unroll
    for (int mi = 0; mi < 2; mi++)
        #pragma unroll
        for (int nj = 0; nj < 8; nj++)
            #pragma unroll
            for (int q = 0; q < 4; q++) c[mi][nj][q] = 0.0f;

    // stage loader: 2048 x 16B chunks, linear (images are pre-swizzled)
    auto load_stage = [&](int ch, int st) {
        const unsigned char* As = Abase + (size_t)ch * A_TILE;
        const unsigned char* Bs = Bbase + (size_t)ch * B_TILE;
        uint32_t dst = sbase + st * STAGE_BYTES;
        #pragma unroll
        for (int q = 0; q < 4; q++) {
            int cix = tid + q * 256;
            cp16(dst + cix * 16, As + (size_t)cix * 16);
        }
        #pragma unroll
        for (int q = 0; q < 4; q++) {
            int cix = tid + q * 256;
            cp16(dst + A_TILE + cix * 16, Bs + (size_t)cix * 16);
        }
    };

    // prologue: stages 0..STG-2
    #pragma unroll
    for (int s = 0; s < STG - 1; s++) { load_stage(s, s); cp_commit(); }

    int st = 0;
    for (int i = 0; i < NCH; i++) {
        cp_wait<STG - 2>();
        __syncthreads();

        // Issue next chunk's copy BEFORE computing: the target stage was
        // consumed in iteration i-1 and the barrier above proves all threads
        // are done with it. Maximizes copy/compute overlap.
        if (i + STG - 1 < NCH) {
            int nst = st + STG - 1; if (nst >= STG) nst -= STG;
            load_stage(i + STG - 1, nst);
        }
        cp_commit();

        uint32_t sb = sbase + st * STAGE_BYTES;
        #pragma unroll
        for (int ks = 0; ks < 4; ks++) {
            uint32_t a[2][4], bf[4][4];
            ldsm_x4(a[0], sb + (offA[0] ^ (ks << 5)));
            ldsm_x4(a[1], sb + (offA[1] ^ (ks << 5)));
            #pragma unroll
            for (int p = 0; p < 4; p++) ldsm_x4_t(bf[p], sb + (offB[ks] ^ (p << 5)));
            #pragma unroll
            for (int mi = 0; mi < 2; mi++)
                #pragma unroll
                for (int p = 0; p < 4; p++) {
                    mma16816(c[mi][2 * p],     a[mi], bf[p][0], bf[p][1]);
                    mma16816(c[mi][2 * p + 1], a[mi], bf[p][2], bf[p][3]);
                }
        }
        if (++st == STG) st = 0;
    }

    // -------- epilogue: (c + bias) * inv, red.v2 scatter-add by token --------
    float bi = bias[e];
    #pragma unroll
    for (int mi = 0; mi < 2; mi++) {
        #pragma unroll
        for (int r = 0; r < 2; r++) {
            int mrow = m_w + mi * 16 + r * 8 + (lane >> 2);
            int gm   = mt * 128 + mrow;
            int tok  = g_idx[(size_t)be * KK + gm];
            float inv = g_inv[(size_t)be * KK + gm];
            float* orow = out + ((size_t)b * SS + tok) * OO + nt * 128 + n_w + (lane & 3) * 2;
            #pragma unroll
            for (int nj = 0; nj < 8; nj++)
                red2(&orow[nj * 8],
                     (c[mi][nj][r * 2]     + bi) * inv,
                     (c[mi][nj][r * 2 + 1] + bi) * inv);
        }
    }
}

// ============================================================================
// Launch: prep(1) -> topk(2) -> gather(3) -> gemm(4)
// ============================================================================
extern "C" void kernel_launch(void* const* d_in, const int* in_sizes, int n_in,
                              void* d_out, int out_size)
{
    const float* x   = (const float*)d_in[0];   // [B,S,D]
    const float* gw  = (const float*)d_in[1];   // [D,E]
    const float* gb  = (const float*)d_in[2];   // [E]
    const float* w   = (const float*)d_in[3];   // [E,D,O]
    const float* bia = (const float*)d_in[4];   // [E,1]
    float* out = (float*)d_out;
    (void)in_sizes; (void)n_in; (void)out_size;

    cudaFuncSetAttribute(gemm_kernel, cudaFuncAttributeMaxDynamicSharedMemorySize, SMEM_DYN);

    prep_kernel<<<BB * SS + EE * 8 * NCH, 256>>>(x, gw, gb, w, out);
    topk_kernel<<<BB * EE, 1024>>>();
    gather_kernel<<<BB * EE * 4 * NCH, 256>>>(x);
    {
        dim3 grid(OO / BN, KK / BM, BB * EE);   // (8, 4, 64)
        gemm_kernel<<<grid, 256, SMEM_DYN>>>(bia, out);
    }
}

// round 9
// speedup vs baseline: 6.9264x; 1.7165x over previous
#include <cuda_runtime.h>
#include <cuda_fp16.h>
#include <cstdint>

// Problem constants
#define BB 4
#define SS 2048
#define DD 1024
#define OO 1024
#define EE 16
#define KK 512

// GEMM tiling (HMMA mma.sync path, baseline sm_100 ISA)
#define BM 128
#define BN 128
#define BK 64
#define NCH 16                     // 1024 / 64 k-chunks
#define STG 3
#define A_TILE 16384               // 128 x 64 halves
#define B_TILE 16384               // 64 x 128 halves (two 64x64 SW128 blocks)
#define STAGE_BYTES (A_TILE + B_TILE)        // 32768
#define SMEM_DYN (STAGE_BYTES * STG)         // 98304

#define GATE_BLOCKS (BB * SS / 8)            // 1024 (8 tokens per block)
#define WCONV_BLOCKS (EE * 8 * NCH)          // 2048

// ---------------- device scratch ----------------
__device__ float g_logits[BB * EE * SS];
__device__ int   g_idx  [BB * EE * KK];
__device__ float g_inv  [BB * EE * KK];
// A images: [be(64)][mt(4)][kc(16)] tiles of [m=128][k=64] halves, SW128   (64 MB)
__device__ __align__(1024) unsigned char g_Ag[64u * 4u * 16u * A_TILE];
// B images: [e(16)][nt(8)][kc(16)] tiles: [h=2][k=64][n=64] halves, SW128  (32 MB)
__device__ __align__(1024) unsigned char g_wt[16u * 8u * 16u * B_TILE];

// ---------------- PTX helpers (baseline ISA only) ----------------
__device__ __forceinline__ uint32_t smem_u32(const void* p) {
    uint32_t a;
    asm("{ .reg .u64 t; cvta.to.shared.u64 t, %1; cvt.u32.u64 %0, t; }" : "=r"(a) : "l"(p));
    return a;
}
__device__ __forceinline__ void cp16(uint32_t dst, const void* src) {
    asm volatile("cp.async.cg.shared.global [%0], [%1], 16;" :: "r"(dst), "l"(src) : "memory");
}
__device__ __forceinline__ void cp_commit() {
    asm volatile("cp.async.commit_group;" ::: "memory");
}
template <int N> __device__ __forceinline__ void cp_wait() {
    asm volatile("cp.async.wait_group %0;" :: "n"(N) : "memory");
}
__device__ __forceinline__ void ldsm_x4(uint32_t* r, uint32_t addr) {
    asm volatile("ldmatrix.sync.aligned.m8n8.x4.shared.b16 {%0,%1,%2,%3}, [%4];"
        : "=r"(r[0]), "=r"(r[1]), "=r"(r[2]), "=r"(r[3]) : "r"(addr));
}
__device__ __forceinline__ void ldsm_x4_t(uint32_t* r, uint32_t addr) {
    asm volatile("ldmatrix.sync.aligned.m8n8.x4.trans.shared.b16 {%0,%1,%2,%3}, [%4];"
        : "=r"(r[0]), "=r"(r[1]), "=r"(r[2]), "=r"(r[3]) : "r"(addr));
}
__device__ __forceinline__ void mma16816(float* c, const uint32_t* a, uint32_t b0, uint32_t b1) {
    asm volatile(
        "mma.sync.aligned.m16n8k16.row.col.f32.f16.f16.f32 "
        "{%0,%1,%2,%3}, {%4,%5,%6,%7}, {%8,%9}, {%0,%1,%2,%3};"
        : "+f"(c[0]), "+f"(c[1]), "+f"(c[2]), "+f"(c[3])
        : "r"(a[0]), "r"(a[1]), "r"(a[2]), "r"(a[3]), "r"(b0), "r"(b1));
}
__device__ __forceinline__ void red2(float* ptr, float a, float b) {
    asm volatile("red.global.add.v2.f32 [%0], {%1, %2};"
        :: "l"(ptr), "f"(a), "f"(b) : "memory");
}
__device__ __forceinline__ int swz(int off) { return off ^ ((off >> 3) & 0x70); }

// ============================================================================
// Kernel 1 (fused prep):
//   blocks [0, 1024): gate for 8 tokens each (warp per token, all 16 experts,
//                     coalesced gw reads) + zero those 8 output rows.
//   blocks [1024, 3072): convert W -> pre-swizzled fp16 B-tile images.
// ============================================================================
__global__ __launch_bounds__(256) void prep_kernel(
    const float* __restrict__ x, const float* __restrict__ gw,
    const float* __restrict__ gb, const float* __restrict__ w,
    float* __restrict__ out)
{
    if (blockIdx.x < GATE_BLOCKS) {
        // ---- gate (8 tokens per block) + zero 8 out rows ----
        int bs0 = blockIdx.x * 8;

        float4* oz = (float4*)(out + (size_t)bs0 * OO);   // 8*1024 floats = 2048 f4
        #pragma unroll
        for (int q = 0; q < 8; q++)
            oz[q * 256 + threadIdx.x] = make_float4(0.f, 0.f, 0.f, 0.f);

        __shared__ float sx[8 * DD];                      // 32 KB
        const float4* xr = (const float4*)(x + (size_t)bs0 * DD);
        #pragma unroll
        for (int q = 0; q < 8; q++)
            ((float4*)sx)[q * 256 + threadIdx.x] = xr[q * 256 + threadIdx.x];
        __syncthreads();

        int wp = threadIdx.x >> 5, l = threadIdx.x & 31;
        int e  = l & 15, dh = l >> 4;                     // expert, d-parity
        int bs = bs0 + wp;
        int b  = bs >> 11, s = bs & (SS - 1);
        const float* xw = sx + wp * DD;

        // Warp-coalesced gw walk: lanes 0..31 hit gw[d*16+0 .. (d+1)*16+15]
        // = 32 consecutive floats = one 128B line per LDG.
        float acc = 0.0f;
        #pragma unroll 8
        for (int it = 0; it < DD / 2; it++) {
            int d = dh + it * 2;
            acc += xw[d] * gw[d * EE + e];
        }
        acc += __shfl_xor_sync(0xffffffffu, acc, 16);     // even-d + odd-d halves
        if (l < 16)
            g_logits[((size_t)(b * EE + l)) * SS + s] = acc + gb[l];
    } else {
        // ---- W conversion ----
        int blk = blockIdx.x - GATE_BLOCKS;
        int kc = blk & 15, nt = (blk >> 4) & 7, e = blk >> 7;
        const float* src = w + ((size_t)e * DD + kc * 64) * OO + (size_t)nt * 128;
        unsigned char* tile = g_wt + (size_t)blk * B_TILE;

        #pragma unroll
        for (int it = 0; it < 4; it++) {
            int u = it * 256 + threadIdx.x;      // 0..1023 : k(64) x c16(16)
            int k = u >> 4, c16 = u & 15;
            const float4* sp = (const float4*)(src + (size_t)k * OO + c16 * 8);
            float4 a = sp[0], c = sp[1];
            __half2 h0 = __floats2half2_rn(a.x, a.y);
            __half2 h1 = __floats2half2_rn(a.z, a.w);
            __half2 h2 = __floats2half2_rn(c.x, c.y);
            __half2 h3 = __floats2half2_rn(c.z, c.w);
            uint4 v;
            v.x = *(uint32_t*)&h0; v.y = *(uint32_t*)&h1;
            v.z = *(uint32_t*)&h2; v.w = *(uint32_t*)&h3;
            int h = c16 >> 3;
            *(uint4*)(tile + h * 8192 + swz(k * 128 + (c16 & 7) * 16)) = v;
        }
    }
}

// ============================================================================
// Kernel 2: softmax stats + exact top-K via bitonic sort per (b,e)
// ============================================================================
__global__ __launch_bounds__(1024) void topk_kernel()
{
    int be = blockIdx.x;
    int t  = threadIdx.x;
    __shared__ float sv[2048];
    __shared__ int   si[2048];
    __shared__ float red[1024];

    const float* lp = g_logits + (size_t)be * SS;
    sv[t] = lp[t]; sv[t + 1024] = lp[t + 1024];
    si[t] = t;     si[t + 1024] = t + 1024;
    __syncthreads();

    float m = fmaxf(sv[t], sv[t + 1024]);
    red[t] = m; __syncthreads();
    for (int s2 = 512; s2 > 0; s2 >>= 1) { if (t < s2) red[t] = fmaxf(red[t], red[t + s2]); __syncthreads(); }
    float gmax = red[0]; __syncthreads();

    float se = expf(sv[t] - gmax) + expf(sv[t + 1024] - gmax);
    red[t] = se; __syncthreads();
    for (int s2 = 512; s2 > 0; s2 >>= 1) { if (t < s2) red[t] += red[t + s2]; __syncthreads(); }
    float gsum = red[0]; __syncthreads();

    for (int k = 2; k <= 2048; k <<= 1) {
        for (int j = k >> 1; j > 0; j >>= 1) {
            #pragma unroll 1
            for (int base = 0; base < 2048; base += 1024) {
                int i = base + t, ixj = i ^ j;
                if (ixj > i) {
                    float vi = sv[i], vj = sv[ixj];
                    int   ii = si[i], ij = si[ixj];
                    bool good = (vi > vj) || (vi == vj && ii < ij);
                    bool dir  = ((i & k) == 0);
                    if (dir ? (!good) : good) {
                        sv[i] = vj; sv[ixj] = vi;
                        si[i] = ij; si[ixj] = ii;
                    }
                }
            }
            __syncthreads();
        }
    }
    if (t < KK) {
        g_idx[(size_t)be * KK + t] = si[t];
        g_inv[(size_t)be * KK + t] = gsum * expf(gmax - sv[t]);
    }
}

// ============================================================================
// Kernel 3: gather + convert x rows -> pre-swizzled fp16 A-tile images
// block = (be, mt, kc); 256 threads
// ============================================================================
__global__ __launch_bounds__(256) void gather_kernel(const float* __restrict__ x)
{
    int blk = blockIdx.x;                 // be*64 + mt*16 + kc
    int kc = blk & 15, mt = (blk >> 4) & 3, be = blk >> 6;
    int b  = be >> 4;
    const int* idx = g_idx + (size_t)be * KK + mt * 128;

    unsigned char* tile = g_Ag + (((size_t)(be * 4 + mt) * NCH + kc) * A_TILE);
    #pragma unroll
    for (int it = 0; it < 4; it++) {
        int u = it * 256 + threadIdx.x;   // 0..1023: 128 rows x 8 16B-chunks
        int row = u >> 3, c16 = u & 7;
        int tok = idx[row];
        const float4* src = (const float4*)(x + ((size_t)b * SS + tok) * DD + kc * 64 + c16 * 8);
        float4 a = src[0], c = src[1];
        __half2 h0 = __floats2half2_rn(a.x, a.y);
        __half2 h1 = __floats2half2_rn(a.z, a.w);
        __half2 h2 = __floats2half2_rn(c.x, c.y);
        __half2 h3 = __floats2half2_rn(c.z, c.w);
        uint4 v;
        v.x = *(uint32_t*)&h0; v.y = *(uint32_t*)&h1;
        v.z = *(uint32_t*)&h2; v.w = *(uint32_t*)&h3;
        *(uint4*)(tile + swz(row * 128 + c16 * 16)) = v;
    }
}

// ============================================================================
// Kernel 4: HMMA GEMM (mma.sync m16n8k16) + red.v2 scatter-add epilogue
// grid = (nt=8, mt=4, be=64); 256 threads = 8 warps in 4(m) x 2(n); 2 CTAs/SM
// ============================================================================
__global__ __launch_bounds__(256, 2) void gemm_kernel(
    const float* __restrict__ bias, float* __restrict__ out)
{
    extern __shared__ unsigned char smem[];
    uint32_t sbase = smem_u32(smem);

    int tid = threadIdx.x, wid = tid >> 5, lane = tid & 31;
    int nt = blockIdx.x, mt = blockIdx.y, be = blockIdx.z;
    int b = be >> 4, e = be & 15;

    const unsigned char* Abase = g_Ag + ((size_t)(be * 4 + mt) * NCH) * A_TILE;
    const unsigned char* Bbase = g_wt + ((size_t)(e * 8 + nt) * NCH) * B_TILE;

    int warp_m = wid >> 1, warp_n = wid & 1;
    int m_w = warp_m * 32, n_w = warp_n * 64;

    // Compact ldmatrix offsets: swz(off + v*32) == swz(off) ^ (v<<5)
    uint32_t offA[2];   // per mi, ks=0; vary ks via ^(ks<<5)
    #pragma unroll
    for (int mi = 0; mi < 2; mi++)
        offA[mi] = swz((m_w + mi * 16 + (lane & 15)) * 128 + (lane >> 4) * 16);
    uint32_t offB[4];   // per ks, p=0; vary p via ^(p<<5)
    #pragma unroll
    for (int ks = 0; ks < 4; ks++)
        offB[ks] = (uint32_t)(A_TILE + warp_n * 8192 +
                   swz((ks * 16 + (lane & 15)) * 128 + (lane >> 4) * 16));

    float c[2][8][4];
    #pragma unroll
    for (int mi = 0; mi < 2; mi++)
        #pragma unroll
        for (int nj = 0; nj < 8; nj++)
            #pragma unroll
            for (int q = 0; q < 4; q++) c[mi][nj][q] = 0.0f;

    // stage loader: 2048 x 16B chunks, linear (images are pre-swizzled)
    auto load_stage = [&](int ch, int st) {
        const unsigned char* As = Abase + (size_t)ch * A_TILE;
        const unsigned char* Bs = Bbase + (size_t)ch * B_TILE;
        uint32_t dst = sbase + st * STAGE_BYTES;
        #pragma unroll
        for (int q = 0; q < 4; q++) {
            int cix = tid + q * 256;
            cp16(dst + cix * 16, As + (size_t)cix * 16);
        }
        #pragma unroll
        for (int q = 0; q < 4; q++) {
            int cix = tid + q * 256;
            cp16(dst + A_TILE + cix * 16, Bs + (size_t)cix * 16);
        }
    };

    // prologue: stages 0..STG-2
    #pragma unroll
    for (int s = 0; s < STG - 1; s++) { load_stage(s, s); cp_commit(); }

    int st = 0;
    for (int i = 0; i < NCH; i++) {
        cp_wait<STG - 2>();
        __syncthreads();

        // Issue next chunk's copy BEFORE computing: the target stage was
        // consumed in iteration i-1 and the barrier above proves all threads
        // are done with it.
        if (i + STG - 1 < NCH) {
            int nst = st + STG - 1; if (nst >= STG) nst -= STG;
            load_stage(i + STG - 1, nst);
        }
        cp_commit();

        uint32_t sb = sbase + st * STAGE_BYTES;
        #pragma unroll
        for (int ks = 0; ks < 4; ks++) {
            uint32_t a[2][4], bf[4][4];
            ldsm_x4(a[0], sb + (offA[0] ^ (ks << 5)));
            ldsm_x4(a[1], sb + (offA[1] ^ (ks << 5)));
            #pragma unroll
            for (int p = 0; p < 4; p++) ldsm_x4_t(bf[p], sb + (offB[ks] ^ (p << 5)));
            #pragma unroll
            for (int mi = 0; mi < 2; mi++)
                #pragma unroll
                for (int p = 0; p < 4; p++) {
                    mma16816(c[mi][2 * p],     a[mi], bf[p][0], bf[p][1]);
                    mma16816(c[mi][2 * p + 1], a[mi], bf[p][2], bf[p][3]);
                }
        }
        if (++st == STG) st = 0;
    }

    // -------- epilogue: (c + bias) * inv, red.v2 scatter-add by token --------
    float bi = bias[e];
    #pragma unroll
    for (int mi = 0; mi < 2; mi++) {
        #pragma unroll
        for (int r = 0; r < 2; r++) {
            int mrow = m_w + mi * 16 + r * 8 + (lane >> 2);
            int gm   = mt * 128 + mrow;
            int tok  = g_idx[(size_t)be * KK + gm];
            float inv = g_inv[(size_t)be * KK + gm];
            float* orow = out + ((size_t)b * SS + tok) * OO + nt * 128 + n_w + (lane & 3) * 2;
            #pragma unroll
            for (int nj = 0; nj < 8; nj++)
                red2(&orow[nj * 8],
                     (c[mi][nj][r * 2]     + bi) * inv,
                     (c[mi][nj][r * 2 + 1] + bi) * inv);
        }
    }
}

// ============================================================================
// Launch: prep(1) -> topk(2) -> gather(3) -> gemm(4)
// ============================================================================
extern "C" void kernel_launch(void* const* d_in, const int* in_sizes, int n_in,
                              void* d_out, int out_size)
{
    const float* x   = (const float*)d_in[0];   // [B,S,D]
    const float* gw  = (const float*)d_in[1];   // [D,E]
    const float* gb  = (const float*)d_in[2];   // [E]
    const float* w   = (const float*)d_in[3];   // [E,D,O]
    const float* bia = (const float*)d_in[4];   // [E,1]
    float* out = (float*)d_out;
    (void)in_sizes; (void)n_in; (void)out_size;

    cudaFuncSetAttribute(gemm_kernel, cudaFuncAttributeMaxDynamicSharedMemorySize, SMEM_DYN);

    prep_kernel<<<GATE_BLOCKS + WCONV_BLOCKS, 256>>>(x, gw, gb, w, out);
    topk_kernel<<<BB * EE, 1024>>>();
    gather_kernel<<<BB * EE * 4 * NCH, 256>>>(x);
    {
        dim3 grid(OO / BN, KK / BM, BB * EE);   // (8, 4, 64)
        gemm_kernel<<<grid, 256, SMEM_DYN>>>(bia, out);
    }
}